// round 11
// baseline (speedup 1.0000x reference)
#include <cuda_runtime.h>
#include <cstdint>

// Problem dims
#define Bv 32
#define Cv 1024
#define Nv 784
#define Mv 4
#define N4v 196      // Nv/4
#define GR 8         // rows per generation (= warps per block)
#define GEN 4        // generations per block
#define BROWS 32     // GR*GEN rows per block
#define CHUNKS 32    // Cv/BROWS
#define GSZ (GR * N4v)   // 1568 float4 per generation buffer

// Scratch (device globals — zero-initialized at load; kC restores zeros)
__device__ float  g_invnorm[Bv][Cv];
__device__ float4 g_t[Bv][Mv][N4v];   // RED-accumulated t (400 KB)
__device__ float4 g_h[Bv][N4v];       // h[b,n] = sum_m g/s

__device__ __forceinline__ void cp_async16(uint32_t saddr, const void* gaddr) {
    asm volatile("cp.async.cg.shared.global [%0], [%1], 16;\n" :: "r"(saddr), "l"(gaddr));
}
__device__ __forceinline__ void cp_commit() {
    asm volatile("cp.async.commit_group;\n");
}
template <int N>
__device__ __forceinline__ void cp_wait() {
    asm volatile("cp.async.wait_group %0;\n" :: "n"(N));
}

extern __shared__ float4 smem_dyn[];  // 3 * GSZ float4 = 75264 B

// ---------------------------------------------------------------------------
// kAB: block = (b, 32-row chunk), 4 generations of 8 rows, TRIPLE-buffered
// cp.async, depth-2 prefetch, 2 barriers/gen. Iteration i runs norms(i) and
// accumulate(i-1) in ONE unbroken compute stretch (different buffers, swsc
// double-buffered). RED-atomic flush into g_t.
// ---------------------------------------------------------------------------
__global__ void __launch_bounds__(256) kAB(const float* __restrict__ x,
                                           const float* __restrict__ Wm) {
    __shared__ float4 swsc[2][GR];
    int b = blockIdx.x, ch = blockIdx.y;
    int p0 = ch * BROWS;
    int t = threadIdx.x;
    int warp = t >> 5, lane = t & 31;
    const float4* base = reinterpret_cast<const float4*>(x) + ((size_t)b * Cv + p0) * N4v;
    uint32_t sbase = (uint32_t)__cvta_generic_to_shared(smem_dyn);

    // depth-2 prologue: prefetch gen0 -> buf0, gen1 -> buf1
#pragma unroll
    for (int gg = 0; gg < 2; ++gg) {
        uint32_t sb = sbase + gg * (GSZ * 16u);
        const float4* gb = base + gg * GSZ;
#pragma unroll
        for (int k = 0; k < 7; ++k) {
            int i = t + k * 256;
            if (i < GSZ) cp_async16(sb + i * 16u, gb + i);
        }
        cp_commit();
    }

    float4 a0 = {0, 0, 0, 0}, a1 = a0, a2 = a0, a3 = a0;

#pragma unroll
    for (int g = 0; g < GEN; ++g) {
        // ensure gen g data has landed
        if (g + 1 < GEN) cp_wait<1>(); else cp_wait<0>();
        __syncthreads();   // BAR(a): gen g visible to all threads

        // ---- norms(gen g): warp w handles row w of buf[g%3] ----
        {
            const float4* cur = smem_dyn + (g % 3) * GSZ + warp * N4v;
            float s = 0.f;
#pragma unroll
            for (int k = 0; k < 7; ++k) {
                int idx = lane + k * 32;
                if (idx < N4v) {
                    float4 v = cur[idx];
                    s += v.x * v.x + v.y * v.y + v.z * v.z + v.w * v.w;
                }
            }
#pragma unroll
            for (int o = 16; o; o >>= 1) s += __shfl_xor_sync(0xffffffffu, s, o);
            if (lane == 0) {
                float inv = 1.0f / fmaxf(sqrtf(s), 1e-10f);
                int p = p0 + g * GR + warp;
                g_invnorm[b][p] = inv;
                float4 w;
                w.x = Wm[0 * Cv + p] * inv;
                w.y = Wm[1 * Cv + p] * inv;
                w.z = Wm[2 * Cv + p] * inv;
                w.w = Wm[3 * Cv + p] * inv;
                swsc[g & 1][warp] = w;
            }
        }

        // ---- accumulate(gen g-1) from buf[(g-1)%3], swsc[(g-1)&1] ----
        if (g > 0 && t < N4v) {
            const float4* prv = smem_dyn + ((g - 1) % 3) * GSZ;
            const float4* wv  = swsc[(g - 1) & 1];
#pragma unroll
            for (int r = 0; r < GR; ++r) {
                float4 w  = wv[r];
                float4 xv = prv[r * N4v + t];
                a0.x = fmaf(w.x, xv.x, a0.x); a0.y = fmaf(w.x, xv.y, a0.y);
                a0.z = fmaf(w.x, xv.z, a0.z); a0.w = fmaf(w.x, xv.w, a0.w);
                a1.x = fmaf(w.y, xv.x, a1.x); a1.y = fmaf(w.y, xv.y, a1.y);
                a1.z = fmaf(w.y, xv.z, a1.z); a1.w = fmaf(w.y, xv.w, a1.w);
                a2.x = fmaf(w.z, xv.x, a2.x); a2.y = fmaf(w.z, xv.y, a2.y);
                a2.z = fmaf(w.z, xv.z, a2.z); a2.w = fmaf(w.z, xv.w, a2.w);
                a3.x = fmaf(w.w, xv.x, a3.x); a3.y = fmaf(w.w, xv.y, a3.y);
                a3.z = fmaf(w.w, xv.z, a3.z); a3.w = fmaf(w.w, xv.w, a3.w);
            }
        }
        __syncthreads();   // BAR(b): swsc(g) published; buf[(g-1)%3] fully consumed

        // issue prefetch(gen g+2) into buf[(g+2)%3] (== buf[(g-1)%3], now free)
        if (g + 2 < GEN) {
            uint32_t sb = sbase + ((g + 2) % 3) * (GSZ * 16u);
            const float4* gb = base + (g + 2) * GSZ;
#pragma unroll
            for (int k = 0; k < 7; ++k) {
                int i = t + k * 256;
                if (i < GSZ) cp_async16(sb + i * 16u, gb + i);
            }
            cp_commit();
        }
    }

    // epilogue: accumulate(gen GEN-1)
    if (t < N4v) {
        const float4* prv = smem_dyn + ((GEN - 1) % 3) * GSZ;
        const float4* wv  = swsc[(GEN - 1) & 1];
#pragma unroll
        for (int r = 0; r < GR; ++r) {
            float4 w  = wv[r];
            float4 xv = prv[r * N4v + t];
            a0.x = fmaf(w.x, xv.x, a0.x); a0.y = fmaf(w.x, xv.y, a0.y);
            a0.z = fmaf(w.x, xv.z, a0.z); a0.w = fmaf(w.x, xv.w, a0.w);
            a1.x = fmaf(w.y, xv.x, a1.x); a1.y = fmaf(w.y, xv.y, a1.y);
            a1.z = fmaf(w.y, xv.z, a1.z); a1.w = fmaf(w.y, xv.w, a1.w);
            a2.x = fmaf(w.z, xv.x, a2.x); a2.y = fmaf(w.z, xv.y, a2.y);
            a2.z = fmaf(w.z, xv.z, a2.z); a2.w = fmaf(w.z, xv.w, a2.w);
            a3.x = fmaf(w.w, xv.x, a3.x); a3.y = fmaf(w.w, xv.y, a3.y);
            a3.z = fmaf(w.w, xv.z, a3.z); a3.w = fmaf(w.w, xv.w, a3.w);
        }
        float* d0 = reinterpret_cast<float*>(&g_t[b][0][t]);
        float* d1 = reinterpret_cast<float*>(&g_t[b][1][t]);
        float* d2 = reinterpret_cast<float*>(&g_t[b][2][t]);
        float* d3 = reinterpret_cast<float*>(&g_t[b][3][t]);
        atomicAdd(d0 + 0, a0.x); atomicAdd(d0 + 1, a0.y);
        atomicAdd(d0 + 2, a0.z); atomicAdd(d0 + 3, a0.w);
        atomicAdd(d1 + 0, a1.x); atomicAdd(d1 + 1, a1.y);
        atomicAdd(d1 + 2, a1.z); atomicAdd(d1 + 3, a1.w);
        atomicAdd(d2 + 0, a2.x); atomicAdd(d2 + 1, a2.y);
        atomicAdd(d2 + 2, a2.z); atomicAdd(d2 + 3, a2.w);
        atomicAdd(d3 + 0, a3.x); atomicAdd(d3 + 1, a3.y);
        atomicAdd(d3 + 2, a3.z); atomicAdd(d3 + 3, a3.w);
    }
}

// ---------------------------------------------------------------------------
// kC: one block per b, 224 threads. Sigmoid, per-model sum of g^2,
// h = sum_m g/s; then RE-ZERO g_t for the next call.
// ---------------------------------------------------------------------------
__global__ void __launch_bounds__(224) kC() {
    int b = blockIdx.x;
    int t = threadIdx.x;
    bool valid = (t < N4v);
    float4 gg0 = {0,0,0,0}, gg1 = gg0, gg2 = gg0, gg3 = gg0;
    if (valid) {
        float4 t0 = g_t[b][0][t], t1 = g_t[b][1][t];
        float4 t2 = g_t[b][2][t], t3 = g_t[b][3][t];
        auto sig4 = [](float4 v) {
            float4 r;
            r.x = 1.f / (1.f + __expf(-v.x));
            r.y = 1.f / (1.f + __expf(-v.y));
            r.z = 1.f / (1.f + __expf(-v.z));
            r.w = 1.f / (1.f + __expf(-v.w));
            return r;
        };
        gg0 = sig4(t0); gg1 = sig4(t1); gg2 = sig4(t2); gg3 = sig4(t3);
    }
    float s0 = gg0.x*gg0.x + gg0.y*gg0.y + gg0.z*gg0.z + gg0.w*gg0.w;
    float s1 = gg1.x*gg1.x + gg1.y*gg1.y + gg1.z*gg1.z + gg1.w*gg1.w;
    float s2 = gg2.x*gg2.x + gg2.y*gg2.y + gg2.z*gg2.z + gg2.w*gg2.w;
    float s3 = gg3.x*gg3.x + gg3.y*gg3.y + gg3.z*gg3.z + gg3.w*gg3.w;
#pragma unroll
    for (int o = 16; o; o >>= 1) {
        s0 += __shfl_xor_sync(0xffffffffu, s0, o);
        s1 += __shfl_xor_sync(0xffffffffu, s1, o);
        s2 += __shfl_xor_sync(0xffffffffu, s2, o);
        s3 += __shfl_xor_sync(0xffffffffu, s3, o);
    }
    __shared__ float sm[4];
    if (t < 4) sm[t] = 0.f;
    __syncthreads();
    if ((t & 31) == 0) {
        atomicAdd(&sm[0], s0);
        atomicAdd(&sm[1], s1);
        atomicAdd(&sm[2], s2);
        atomicAdd(&sm[3], s3);
    }
    __syncthreads();
    if (valid) {
        float i0 = 1.f / sm[0], i1 = 1.f / sm[1], i2 = 1.f / sm[2], i3 = 1.f / sm[3];
        float4 h;
        h.x = gg0.x*i0 + gg1.x*i1 + gg2.x*i2 + gg3.x*i3;
        h.y = gg0.y*i0 + gg1.y*i1 + gg2.y*i2 + gg3.y*i3;
        h.z = gg0.z*i0 + gg1.z*i1 + gg2.z*i2 + gg3.z*i3;
        h.w = gg0.w*i0 + gg1.w*i1 + gg2.w*i2 + gg3.w*i3;
        g_h[b][t] = h;
        float4 z = {0, 0, 0, 0};
        g_t[b][0][t] = z; g_t[b][1][t] = z;
        g_t[b][2][t] = z; g_t[b][3][t] = z;
    }
}

// ---------------------------------------------------------------------------
// kD: barrier-free final dot (R8, proven). Grid (32, 32), 512 threads; each
// warp streams TWO rows interleaved; h via __ldg (L1-hot).
// ---------------------------------------------------------------------------
__global__ void __launch_bounds__(512) kD(const float* __restrict__ x,
                                          float* __restrict__ out) {
    int b = blockIdx.x;
    int warp = threadIdx.x >> 5, lane = threadIdx.x & 31;
    int p = (blockIdx.y << 5) + (warp << 1);   // rows p and p+1
    const float4* r0 = reinterpret_cast<const float4*>(x) + ((size_t)b * Cv + p) * N4v;
    const float4* r1 = r0 + N4v;
    const float4* hb = &g_h[b][0];
    float s0 = 0.f, s1 = 0.f;
#pragma unroll
    for (int k = 0; k < 6; ++k) {
        int idx = lane + k * 32;
        float4 a = r0[idx], c = r1[idx];
        float4 h = __ldg(hb + idx);
        s0 += a.x * h.x + a.y * h.y + a.z * h.z + a.w * h.w;
        s1 += c.x * h.x + c.y * h.y + c.z * h.z + c.w * h.w;
    }
    if (lane < 4) {
        int idx = 192 + lane;
        float4 a = r0[idx], c = r1[idx];
        float4 h = __ldg(hb + idx);
        s0 += a.x * h.x + a.y * h.y + a.z * h.z + a.w * h.w;
        s1 += c.x * h.x + c.y * h.y + c.z * h.z + c.w * h.w;
    }
#pragma unroll
    for (int o = 16; o; o >>= 1) {
        s0 += __shfl_xor_sync(0xffffffffu, s0, o);
        s1 += __shfl_xor_sync(0xffffffffu, s1, o);
    }
    if (lane == 0) {
        out[b * Cv + p]     = s0 * g_invnorm[b][p];
        out[b * Cv + p + 1] = s1 * g_invnorm[b][p + 1];
    }
}

extern "C" void kernel_launch(void* const* d_in, const int* in_sizes, int n_in,
                              void* d_out, int out_size) {
    const float* x  = (const float*)d_in[0];   // [32,1024,28,28] f32
    const float* Wm = (const float*)d_in[1];   // [4,1,1024] f32
    float* out = (float*)d_out;                // [32,1024] f32

    static const int smem_bytes = 3 * GSZ * sizeof(float4);  // 75264
    cudaFuncSetAttribute(kAB, cudaFuncAttributeMaxDynamicSharedMemorySize, smem_bytes);

    kAB<<<dim3(32, CHUNKS), 256, smem_bytes>>>(x, Wm);
    kC<<<32, 224>>>();
    kD<<<dim3(32, 32), 512>>>(x, out);
}